// round 5
// baseline (speedup 1.0000x reference)
#include <cuda_runtime.h>
#include <cuda_bf16.h>
#include <math.h>

#define BATCH 1024
#define SEQ   1024
#define TAGS  32
#define NW    4     // warps per block

// Device scratch (allocation-free per harness rules)
__device__ float g_logz[BATCH];
__device__ float g_partial[BATCH];

// ---------- packed f32x2 helpers (sm_103a FFMA2 path, PTX-only) ----------
__device__ __forceinline__ unsigned long long pk2(float x, float y) {
    unsigned long long r;
    asm("mov.b64 %0, {%1, %2};" : "=l"(r) : "f"(x), "f"(y));
    return r;
}
__device__ __forceinline__ void upk2(unsigned long long a, float& x, float& y) {
    asm("mov.b64 {%0, %1}, %2;" : "=f"(x), "=f"(y) : "l"(a));
}
__device__ __forceinline__ unsigned long long mul2(unsigned long long a, unsigned long long b) {
    unsigned long long d;
    asm("mul.rn.f32x2 %0, %1, %2;" : "=l"(d) : "l"(a), "l"(b));
    return d;
}
__device__ __forceinline__ unsigned long long fma2(unsigned long long a, unsigned long long b, unsigned long long c) {
    unsigned long long d;
    asm("fma.rn.f32x2 %0, %1, %2, %3;" : "=l"(d) : "l"(a), "l"(b), "l"(c));
    return d;
}
__device__ __forceinline__ unsigned long long add2(unsigned long long a, unsigned long long b) {
    unsigned long long d;
    asm("add.rn.f32x2 %0, %1, %2;" : "=l"(d) : "l"(a), "l"(b));
    return d;
}
// MUFU intrinsics, forced
__device__ __forceinline__ float ex2f(float x) {
    float y; asm("ex2.approx.f32 %0, %1;" : "=f"(y) : "f"(x)); return y;
}
__device__ __forceinline__ float lg2f(float x) {
    float y; asm("lg2.approx.f32 %0, %1;" : "=f"(y) : "f"(x)); return y;
}

// ---------------------------------------------------------------------------
// Kernel 1: forward algorithm. One warp per batch, lane = tag.
// Prob-space recursion: s_j = sum_i exp(v_i - m) * E[i][j],
//                       v'_j = m + ln(s_j) + emit_j
// m is a (1-step-stale) broadcast of lane-0's v: keeps exp in fp32 range and
// keeps the SHFL off the loop-carried critical path.
// ---------------------------------------------------------------------------
__global__ __launch_bounds__(NW * 32, 1)
void crf_forward_kernel(const float* __restrict__ logits,
                        const float* __restrict__ trans) {
    const int warp = threadIdx.x >> 5;
    const int j    = threadIdx.x & 31;
    const int b    = blockIdx.x * NW + warp;

    // E column j, packed in pairs over i: e[k] = { E[2k][j], E[2k+1][j] }
    unsigned long long e[16];
#pragma unroll
    for (int k = 0; k < 16; k++) {
        float a0 = expf(trans[(2 * k + 0) * TAGS + j]);
        float a1 = expf(trans[(2 * k + 1) * TAGS + j]);
        e[k] = pk2(a0, a1);
    }

    __shared__ float4 wbuf[NW][2][8];   // double-buffered w row per warp
    float* wb0 = (float*)&wbuf[warp][0][0];
    float* wb1 = (float*)&wbuf[warp][1][0];

    const float* lg = logits + (size_t)b * (SEQ * TAGS);

    float v = lg[j];                                   // t = 0
    float m      = __shfl_sync(0xffffffffu, v, 0);
    float m_next = m;

    // emit prefetch ring, depth 4 (covers DRAM latency under ~4 step-chains)
    float p0 = lg[1 * TAGS + j];
    float p1 = lg[2 * TAGS + j];
    float p2 = lg[3 * TAGS + j];
    float p3 = lg[4 * TAGS + j];

#pragma unroll 4
    for (int t = 1; t < SEQ; t++) {
        float emit = p0;
        p0 = p1; p1 = p2; p2 = p3;
        p3 = (t + 4 < SEQ) ? lg[(t + 4) * TAGS + j] : 0.0f;

        // w_j = exp(v_j - m)  via EX2
        float w = ex2f((v - m) * 1.4426950408889634f);
        float* wb = (t & 1) ? wb1 : wb0;
        wb[j] = w;
        __syncwarp(0xffffffffu);

        // s_j = sum_i w_i * E[i][j]  — 8x LDS.128 broadcast + 16 packed FMA2
        const float4* w4 = (const float4*)wb;
        unsigned long long acc0, acc1, acc2, acc3;
        {
            float4 q0 = w4[0], q1 = w4[1], q2 = w4[2], q3 = w4[3];
            acc0 = mul2(pk2(q0.x, q0.y), e[0]);
            acc1 = mul2(pk2(q0.z, q0.w), e[1]);
            acc2 = mul2(pk2(q1.x, q1.y), e[2]);
            acc3 = mul2(pk2(q1.z, q1.w), e[3]);
            acc0 = fma2(pk2(q2.x, q2.y), e[4], acc0);
            acc1 = fma2(pk2(q2.z, q2.w), e[5], acc1);
            acc2 = fma2(pk2(q3.x, q3.y), e[6], acc2);
            acc3 = fma2(pk2(q3.z, q3.w), e[7], acc3);
            float4 q4 = w4[4], q5 = w4[5], q6 = w4[6], q7 = w4[7];
            acc0 = fma2(pk2(q4.x, q4.y), e[8],  acc0);
            acc1 = fma2(pk2(q4.z, q4.w), e[9],  acc1);
            acc2 = fma2(pk2(q5.x, q5.y), e[10], acc2);
            acc3 = fma2(pk2(q5.z, q5.w), e[11], acc3);
            acc0 = fma2(pk2(q6.x, q6.y), e[12], acc0);
            acc1 = fma2(pk2(q6.z, q6.w), e[13], acc1);
            acc2 = fma2(pk2(q7.x, q7.y), e[14], acc2);
            acc3 = fma2(pk2(q7.z, q7.w), e[15], acc3);
        }
        acc0 = add2(acc0, acc1);
        acc2 = add2(acc2, acc3);
        acc0 = add2(acc0, acc2);
        float slo, shi;
        upk2(acc0, slo, shi);
        float s = slo + shi;

        // v'_j = m + ln(s) + emit  (ln via LG2 * ln2)
        v = fmaf(lg2f(s), 0.6931471805599453f, m + emit);

        // rotate stale scale; SHFL result consumed a full iteration later
        m      = m_next;
        m_next = __shfl_sync(0xffffffffu, v, 0);
    }

    // log_z = logsumexp over tags (exact max here)
    float mx = v;
#pragma unroll
    for (int k = 16; k; k >>= 1)
        mx = fmaxf(mx, __shfl_xor_sync(0xffffffffu, mx, k));
    float ex = ex2f((v - mx) * 1.4426950408889634f);
#pragma unroll
    for (int k = 16; k; k >>= 1)
        ex += __shfl_xor_sync(0xffffffffu, ex, k);
    if (j == 0)
        g_logz[b] = fmaf(lg2f(ex), 0.6931471805599453f, mx);
}

// ---------------------------------------------------------------------------
// Kernel 2: gold score per batch, then partial[b] = logz[b] - gold[b].
// Warp per batch, lanes stride over sequence positions.
// ---------------------------------------------------------------------------
__global__ __launch_bounds__(NW * 32, 1)
void crf_gold_kernel(const float* __restrict__ logits,
                     const float* __restrict__ trans,
                     const int* __restrict__ tags,
                     const int* __restrict__ lengths) {
    __shared__ float tr[TAGS * TAGS];
    for (int i = threadIdx.x; i < TAGS * TAGS; i += blockDim.x)
        tr[i] = trans[i];
    __syncthreads();

    const int warp = threadIdx.x >> 5;
    const int l    = threadIdx.x & 31;
    const int b    = blockIdx.x * NW + warp;

    const int*   tg = tags + (size_t)b * SEQ;
    const float* lg = logits + (size_t)b * (SEQ * TAGS);
    const int len = lengths[b];

    float acc = 0.0f;
    for (int s = l; s < len; s += 32) {
        int t1 = tg[s];
        acc += lg[s * TAGS + t1];
        if (s > 0) {
            int t0 = tg[s - 1];
            acc += tr[t0 * TAGS + t1];
        }
    }
#pragma unroll
    for (int k = 16; k; k >>= 1)
        acc += __shfl_xor_sync(0xffffffffu, acc, k);
    if (l == 0)
        g_partial[b] = g_logz[b] - acc;
}

// ---------------------------------------------------------------------------
// Kernel 3: deterministic tree reduction -> mean
// ---------------------------------------------------------------------------
__global__ void crf_reduce_kernel(float* __restrict__ out) {
    __shared__ float sm[256];
    int tid = threadIdx.x;
    float a = g_partial[tid] + g_partial[tid + 256] +
              g_partial[tid + 512] + g_partial[tid + 768];
    sm[tid] = a;
    __syncthreads();
#pragma unroll
    for (int k = 128; k; k >>= 1) {
        if (tid < k) sm[tid] += sm[tid + k];
        __syncthreads();
    }
    if (tid == 0) out[0] = sm[0] * (1.0f / 1024.0f);
}

extern "C" void kernel_launch(void* const* d_in, const int* in_sizes, int n_in,
                              void* d_out, int out_size) {
    const float* logits  = (const float*)d_in[0];
    const float* trans   = (const float*)d_in[1];
    const int*   tags    = (const int*)d_in[2];
    const int*   lengths = (const int*)d_in[3];
    float* out = (float*)d_out;

    crf_forward_kernel<<<BATCH / NW, NW * 32>>>(logits, trans);
    crf_gold_kernel<<<BATCH / NW, NW * 32>>>(logits, trans, tags, lengths);
    crf_reduce_kernel<<<1, 256>>>(out);
}

// round 6
// speedup vs baseline: 1.8301x; 1.8301x over previous
#include <cuda_runtime.h>
#include <cuda_bf16.h>
#include <math.h>

#define BATCH 1024
#define SEQ   1024
#define TAGS  32
#define HALF  512          // meeting point
#define ITERS 511          // main-loop iterations per direction
#define NW    4            // warps per block in gold kernel

__device__ float g_logz[BATCH];
__device__ float g_partial[BATCH];

// ---------- packed f32x2 helpers (sm_103a FFMA2 path, PTX-only) ----------
__device__ __forceinline__ unsigned long long pk2(float x, float y) {
    unsigned long long r;
    asm("mov.b64 %0, {%1, %2};" : "=l"(r) : "f"(x), "f"(y));
    return r;
}
__device__ __forceinline__ void upk2(unsigned long long a, float& x, float& y) {
    asm("mov.b64 {%0, %1}, %2;" : "=f"(x), "=f"(y) : "l"(a));
}
__device__ __forceinline__ float lo32(unsigned long long a) {
    float x, y; upk2(a, x, y); return x;
}
__device__ __forceinline__ unsigned long long mul2(unsigned long long a, unsigned long long b) {
    unsigned long long d;
    asm("mul.rn.f32x2 %0, %1, %2;" : "=l"(d) : "l"(a), "l"(b));
    return d;
}
__device__ __forceinline__ unsigned long long fma2(unsigned long long a, unsigned long long b, unsigned long long c) {
    unsigned long long d;
    asm("fma.rn.f32x2 %0, %1, %2, %3;" : "=l"(d) : "l"(a), "l"(b), "l"(c));
    return d;
}
__device__ __forceinline__ unsigned long long add2(unsigned long long a, unsigned long long b) {
    unsigned long long d;
    asm("add.rn.f32x2 %0, %1, %2;" : "=l"(d) : "l"(a), "l"(b));
    return d;
}
__device__ __forceinline__ float ex2f(float x) {
    float y; asm("ex2.approx.f32 %0, %1;" : "=f"(y) : "f"(x)); return y;
}
__device__ __forceinline__ float lg2f(float x) {
    float y; asm("lg2.approx.f32 %0, %1;" : "=f"(y) : "f"(x)); return y;
}
__device__ __forceinline__ float rcpf(float x) {
    float y; asm("rcp.approx.f32 %0, %1;" : "=f"(y) : "f"(x)); return y;
}

#define LOG2E 1.4426950408889634f
#define LN2   0.6931471805599453f

// shared matvec: s_j = sum_i w_i * e-pairs (w already in wb, synced by caller)
__device__ __forceinline__ float matvec32(const float* wb, const unsigned long long* e) {
    const ulonglong2* w4 = (const ulonglong2*)wb;
    ulonglong2 q0 = w4[0], q1 = w4[1], q2 = w4[2], q3 = w4[3];
    unsigned long long a0 = mul2(q0.x, e[0]);
    unsigned long long a1 = mul2(q0.y, e[1]);
    unsigned long long a2 = mul2(q1.x, e[2]);
    unsigned long long a3 = mul2(q1.y, e[3]);
    a0 = fma2(q2.x, e[4], a0);
    a1 = fma2(q2.y, e[5], a1);
    a2 = fma2(q3.x, e[6], a2);
    a3 = fma2(q3.y, e[7], a3);
    ulonglong2 q4 = w4[4], q5 = w4[5], q6 = w4[6], q7 = w4[7];
    a0 = fma2(q4.x, e[8],  a0);
    a1 = fma2(q4.y, e[9],  a1);
    a2 = fma2(q5.x, e[10], a2);
    a3 = fma2(q5.y, e[11], a3);
    a0 = fma2(q6.x, e[12], a0);
    a1 = fma2(q6.y, e[13], a1);
    a2 = fma2(q7.x, e[14], a2);
    a3 = fma2(q7.y, e[15], a3);
    a0 = add2(a0, a1);
    a2 = add2(a2, a3);
    a0 = add2(a0, a2);
    float slo, shi;
    upk2(a0, slo, shi);
    return slo + shi;
}

// ---------------------------------------------------------------------------
// Forward+backward kernel. 2 batches per block (128 threads):
//   warp 0: fwd batch b0   warp 1: bwd batch b0
//   warp 2: fwd batch b1   warp 3: bwd batch b1
// Probability-space recursions, renorm every 4 steps from the broadcast u[0]:
//   fwd: u_t(j)     = p_t(j) * sum_i u_{t-1}(i) E[i][j]
//   bwd: gamma_t(i) = q_t(i) * sum_j E[i][j] gamma_{t+1}(j)
// Meet: Z = sum_k (E^T alpha_511)_k gamma_512(k)
// ---------------------------------------------------------------------------
__global__ __launch_bounds__(128, 4)
void crf_fb_kernel(const float* __restrict__ logits,
                   const float* __restrict__ trans) {
    const int w   = threadIdx.x >> 5;     // warp in block (0..3)
    const int j   = threadIdx.x & 31;     // lane = tag
    const int bi  = w >> 1;               // batch within block (0/1)
    const int dir = w & 1;                // 0 = fwd, 1 = bwd
    const int b   = blockIdx.x * 2 + bi;

    __shared__ __align__(16) float sbuf[4][2][32];  // [warp][parity][vec]
    __shared__ float xg[2][32];                     // gamma_512 exchange
    __shared__ float xacc[2];                       // logaccB exchange

    // E operand registers (pairs packed for fma2):
    //  fwd: e[k] = { E[2k][j],   E[2k+1][j] }   (pairs over i, column j)
    //  bwd: e[k] = { E[j][2k],   E[j][2k+1] }   (pairs over j', row i=lane)
    unsigned long long e[16];
    if (dir == 0) {
#pragma unroll
        for (int k = 0; k < 16; k++)
            e[k] = pk2(expf(trans[(2 * k)     * TAGS + j]),
                       expf(trans[(2 * k + 1) * TAGS + j]));
    } else {
#pragma unroll
        for (int k = 0; k < 16; k++)
            e[k] = pk2(expf(trans[j * TAGS + 2 * k]),
                       expf(trans[j * TAGS + 2 * k + 1]));
    }

    const float* lg = logits + (size_t)b * (SEQ * TAGS);

    // init state (scaled by lane-0 emit)
    float e0 = (dir == 0) ? lg[j] : lg[(SEQ - 1) * TAGS + j];
    float m0 = __shfl_sync(0xffffffffu, e0, 0);
    float u      = ex2f((e0 - m0) * LOG2E);
    float logacc = m0;

    // emit stream: fwd t = 1,2,...   bwd t = 1022,1021,...
    const float* ep = (dir == 0) ? (lg + TAGS + j)
                                 : (lg + (SEQ - 2) * TAGS + j);
    const int estep = (dir == 0) ? TAGS : -TAGS;

    // prefetch ring depth 4 (over-reads at the tail stay in-bounds, unused)
    float r0 = ep[0];
    float r1 = ep[estep];
    float r2 = ep[2 * estep];
    float r3 = ep[3 * estep];
    const float* pl = ep + 4 * estep;

    float* wb0 = &sbuf[w][0][0];
    float* wb1 = &sbuf[w][1][0];

#pragma unroll 4
    for (int it = 0; it < ITERS; ++it) {
        float emit = r0;
        r0 = r1; r1 = r2; r2 = r3;
        r3 = *pl; pl += estep;

        float p = ex2f(emit * LOG2E);       // off the carried chain

        float* wb = (it & 1) ? wb1 : wb0;
        wb[j] = u;
        __syncwarp(0xffffffffu);

        // need q0 again for renorm: matvec32 reads it; re-read lo element
        float s = matvec32(wb, e);
        float un = s * p;

        if ((it & 3) == 0) {
            float u0 = wb[0];               // broadcast hit, same line as matvec
            un *= rcpf(u0);
            logacc += lg2f(u0) * LN2;       // off-path bookkeeping
        }
        u = un;
    }

    // final renorm so the meeting dot-product can't overflow
    {
        float u0 = __shfl_sync(0xffffffffu, u, 0);
        u *= rcpf(u0);
        logacc += lg2f(u0) * LN2;
    }

    if (dir == 1) {
        xg[bi][j] = u;                      // gamma_512 (scaled)
        if (j == 0) xacc[bi] = logacc;
    }
    __syncthreads();

    if (dir == 0) {
        // s = E^T alpha_511  (one more matvec, no emit). Use parity-1 buffer:
        // its last reads (it=509) are sealed by syncwarp(it=510).
        wb1[j] = u;
        __syncwarp(0xffffffffu);
        float s = matvec32(wb1, e);

        float prod = s * xg[bi][j];
#pragma unroll
        for (int k = 16; k; k >>= 1)
            prod += __shfl_xor_sync(0xffffffffu, prod, k);

        if (j == 0)
            g_logz[b] = lg2f(prod) * LN2 + logacc + xacc[bi];
    }
}

// ---------------------------------------------------------------------------
// Gold score per batch: partial[b] = logz[b] - gold[b]
// ---------------------------------------------------------------------------
__global__ __launch_bounds__(NW * 32, 1)
void crf_gold_kernel(const float* __restrict__ logits,
                     const float* __restrict__ trans,
                     const int* __restrict__ tags,
                     const int* __restrict__ lengths) {
    __shared__ float tr[TAGS * TAGS];
    for (int i = threadIdx.x; i < TAGS * TAGS; i += blockDim.x)
        tr[i] = trans[i];
    __syncthreads();

    const int warp = threadIdx.x >> 5;
    const int l    = threadIdx.x & 31;
    const int b    = blockIdx.x * NW + warp;

    const int*   tg = tags + (size_t)b * SEQ;
    const float* lg = logits + (size_t)b * (SEQ * TAGS);
    const int len = lengths[b];

    float acc = 0.0f;
    for (int s = l; s < len; s += 32) {
        int t1 = tg[s];
        acc += lg[s * TAGS + t1];
        if (s > 0) {
            int t0 = tg[s - 1];
            acc += tr[t0 * TAGS + t1];
        }
    }
#pragma unroll
    for (int k = 16; k; k >>= 1)
        acc += __shfl_xor_sync(0xffffffffu, acc, k);
    if (l == 0)
        g_partial[b] = g_logz[b] - acc;
}

// ---------------------------------------------------------------------------
// Deterministic tree reduction -> mean
// ---------------------------------------------------------------------------
__global__ void crf_reduce_kernel(float* __restrict__ out) {
    __shared__ float sm[256];
    int tid = threadIdx.x;
    float a = g_partial[tid] + g_partial[tid + 256] +
              g_partial[tid + 512] + g_partial[tid + 768];
    sm[tid] = a;
    __syncthreads();
#pragma unroll
    for (int k = 128; k; k >>= 1) {
        if (tid < k) sm[tid] += sm[tid + k];
        __syncthreads();
    }
    if (tid == 0) out[0] = sm[0] * (1.0f / 1024.0f);
}

extern "C" void kernel_launch(void* const* d_in, const int* in_sizes, int n_in,
                              void* d_out, int out_size) {
    const float* logits  = (const float*)d_in[0];
    const float* trans   = (const float*)d_in[1];
    const int*   tags    = (const int*)d_in[2];
    const int*   lengths = (const int*)d_in[3];
    float* out = (float*)d_out;

    crf_fb_kernel<<<BATCH / 2, 128>>>(logits, trans);
    crf_gold_kernel<<<BATCH / NW, NW * 32>>>(logits, trans, tags, lengths);
    crf_reduce_kernel<<<1, 256>>>(out);
}

// round 7
// speedup vs baseline: 1.8379x; 1.0043x over previous
#include <cuda_runtime.h>
#include <cuda_bf16.h>
#include <math.h>

#define BATCH 1024
#define SEQ   1024
#define TAGS  32
#define HALF  512          // meeting point
#define ITERS 511          // main-loop iterations per direction
#define NW    4            // warps per block in gold kernel

__device__ float g_logz[BATCH];
__device__ float g_partial[BATCH];

// ---------- packed f32x2 helpers (sm_103a FFMA2 path, PTX-only) ----------
__device__ __forceinline__ unsigned long long pk2(float x, float y) {
    unsigned long long r;
    asm("mov.b64 %0, {%1, %2};" : "=l"(r) : "f"(x), "f"(y));
    return r;
}
__device__ __forceinline__ void upk2(unsigned long long a, float& x, float& y) {
    asm("mov.b64 {%0, %1}, %2;" : "=f"(x), "=f"(y) : "l"(a));
}
__device__ __forceinline__ float lo32(unsigned long long a) {
    float x, y; upk2(a, x, y); return x;
}
__device__ __forceinline__ unsigned long long mul2(unsigned long long a, unsigned long long b) {
    unsigned long long d;
    asm("mul.rn.f32x2 %0, %1, %2;" : "=l"(d) : "l"(a), "l"(b));
    return d;
}
__device__ __forceinline__ unsigned long long fma2(unsigned long long a, unsigned long long b, unsigned long long c) {
    unsigned long long d;
    asm("fma.rn.f32x2 %0, %1, %2, %3;" : "=l"(d) : "l"(a), "l"(b), "l"(c));
    return d;
}
__device__ __forceinline__ unsigned long long add2(unsigned long long a, unsigned long long b) {
    unsigned long long d;
    asm("add.rn.f32x2 %0, %1, %2;" : "=l"(d) : "l"(a), "l"(b));
    return d;
}
__device__ __forceinline__ float ex2f(float x) {
    float y; asm("ex2.approx.f32 %0, %1;" : "=f"(y) : "f"(x)); return y;
}
__device__ __forceinline__ float lg2f(float x) {
    float y; asm("lg2.approx.f32 %0, %1;" : "=f"(y) : "f"(x)); return y;
}
__device__ __forceinline__ float rcpf(float x) {
    float y; asm("rcp.approx.f32 %0, %1;" : "=f"(y) : "f"(x)); return y;
}

#define LOG2E 1.4426950408889634f
#define LN2   0.6931471805599453f

// shared matvec: s_j = sum_i w_i * e-pairs (w already in wb, synced by caller)
__device__ __forceinline__ float matvec32(const float* wb, const unsigned long long* e) {
    const ulonglong2* w4 = (const ulonglong2*)wb;
    ulonglong2 q0 = w4[0], q1 = w4[1], q2 = w4[2], q3 = w4[3];
    unsigned long long a0 = mul2(q0.x, e[0]);
    unsigned long long a1 = mul2(q0.y, e[1]);
    unsigned long long a2 = mul2(q1.x, e[2]);
    unsigned long long a3 = mul2(q1.y, e[3]);
    a0 = fma2(q2.x, e[4], a0);
    a1 = fma2(q2.y, e[5], a1);
    a2 = fma2(q3.x, e[6], a2);
    a3 = fma2(q3.y, e[7], a3);
    ulonglong2 q4 = w4[4], q5 = w4[5], q6 = w4[6], q7 = w4[7];
    a0 = fma2(q4.x, e[8],  a0);
    a1 = fma2(q4.y, e[9],  a1);
    a2 = fma2(q5.x, e[10], a2);
    a3 = fma2(q5.y, e[11], a3);
    a0 = fma2(q6.x, e[12], a0);
    a1 = fma2(q6.y, e[13], a1);
    a2 = fma2(q7.x, e[14], a2);
    a3 = fma2(q7.y, e[15], a3);
    a0 = add2(a0, a1);
    a2 = add2(a2, a3);
    a0 = add2(a0, a2);
    float slo, shi;
    upk2(a0, slo, shi);
    return slo + shi;
}

// ---------------------------------------------------------------------------
// Forward+backward kernel. 2 batches per block (128 threads):
//   warp 0: fwd batch b0   warp 1: bwd batch b0
//   warp 2: fwd batch b1   warp 3: bwd batch b1
// Probability-space recursions, renorm every 4 steps from the broadcast u[0]:
//   fwd: u_t(j)     = p_t(j) * sum_i u_{t-1}(i) E[i][j]
//   bwd: gamma_t(i) = q_t(i) * sum_j E[i][j] gamma_{t+1}(j)
// Meet: Z = sum_k (E^T alpha_511)_k gamma_512(k)
// ---------------------------------------------------------------------------
__global__ __launch_bounds__(128, 4)
void crf_fb_kernel(const float* __restrict__ logits,
                   const float* __restrict__ trans) {
    const int w   = threadIdx.x >> 5;     // warp in block (0..3)
    const int j   = threadIdx.x & 31;     // lane = tag
    const int bi  = w >> 1;               // batch within block (0/1)
    const int dir = w & 1;                // 0 = fwd, 1 = bwd
    const int b   = blockIdx.x * 2 + bi;

    __shared__ __align__(16) float sbuf[4][2][32];  // [warp][parity][vec]
    __shared__ float xg[2][32];                     // gamma_512 exchange
    __shared__ float xacc[2];                       // logaccB exchange

    // E operand registers (pairs packed for fma2):
    //  fwd: e[k] = { E[2k][j],   E[2k+1][j] }   (pairs over i, column j)
    //  bwd: e[k] = { E[j][2k],   E[j][2k+1] }   (pairs over j', row i=lane)
    unsigned long long e[16];
    if (dir == 0) {
#pragma unroll
        for (int k = 0; k < 16; k++)
            e[k] = pk2(expf(trans[(2 * k)     * TAGS + j]),
                       expf(trans[(2 * k + 1) * TAGS + j]));
    } else {
#pragma unroll
        for (int k = 0; k < 16; k++)
            e[k] = pk2(expf(trans[j * TAGS + 2 * k]),
                       expf(trans[j * TAGS + 2 * k + 1]));
    }

    const float* lg = logits + (size_t)b * (SEQ * TAGS);

    // init state (scaled by lane-0 emit)
    float e0 = (dir == 0) ? lg[j] : lg[(SEQ - 1) * TAGS + j];
    float m0 = __shfl_sync(0xffffffffu, e0, 0);
    float u      = ex2f((e0 - m0) * LOG2E);
    float logacc = m0;

    // emit stream: fwd t = 1,2,...   bwd t = 1022,1021,...
    const float* ep = (dir == 0) ? (lg + TAGS + j)
                                 : (lg + (SEQ - 2) * TAGS + j);
    const int estep = (dir == 0) ? TAGS : -TAGS;

    // prefetch ring depth 4 (over-reads at the tail stay in-bounds, unused)
    float r0 = ep[0];
    float r1 = ep[estep];
    float r2 = ep[2 * estep];
    float r3 = ep[3 * estep];
    const float* pl = ep + 4 * estep;

    float* wb0 = &sbuf[w][0][0];
    float* wb1 = &sbuf[w][1][0];

#pragma unroll 4
    for (int it = 0; it < ITERS; ++it) {
        float emit = r0;
        r0 = r1; r1 = r2; r2 = r3;
        r3 = *pl; pl += estep;

        float p = ex2f(emit * LOG2E);       // off the carried chain

        float* wb = (it & 1) ? wb1 : wb0;
        wb[j] = u;
        __syncwarp(0xffffffffu);

        // need q0 again for renorm: matvec32 reads it; re-read lo element
        float s = matvec32(wb, e);
        float un = s * p;

        if ((it & 3) == 0) {
            float u0 = wb[0];               // broadcast hit, same line as matvec
            un *= rcpf(u0);
            logacc += lg2f(u0) * LN2;       // off-path bookkeeping
        }
        u = un;
    }

    // final renorm so the meeting dot-product can't overflow
    {
        float u0 = __shfl_sync(0xffffffffu, u, 0);
        u *= rcpf(u0);
        logacc += lg2f(u0) * LN2;
    }

    if (dir == 1) {
        xg[bi][j] = u;                      // gamma_512 (scaled)
        if (j == 0) xacc[bi] = logacc;
    }
    __syncthreads();

    if (dir == 0) {
        // s = E^T alpha_511  (one more matvec, no emit). Use parity-1 buffer:
        // its last reads (it=509) are sealed by syncwarp(it=510).
        wb1[j] = u;
        __syncwarp(0xffffffffu);
        float s = matvec32(wb1, e);

        float prod = s * xg[bi][j];
#pragma unroll
        for (int k = 16; k; k >>= 1)
            prod += __shfl_xor_sync(0xffffffffu, prod, k);

        if (j == 0)
            g_logz[b] = lg2f(prod) * LN2 + logacc + xacc[bi];
    }
}

// ---------------------------------------------------------------------------
// Gold score per batch: partial[b] = logz[b] - gold[b]
// ---------------------------------------------------------------------------
__global__ __launch_bounds__(NW * 32, 1)
void crf_gold_kernel(const float* __restrict__ logits,
                     const float* __restrict__ trans,
                     const int* __restrict__ tags,
                     const int* __restrict__ lengths) {
    __shared__ float tr[TAGS * TAGS];
    for (int i = threadIdx.x; i < TAGS * TAGS; i += blockDim.x)
        tr[i] = trans[i];
    __syncthreads();

    const int warp = threadIdx.x >> 5;
    const int l    = threadIdx.x & 31;
    const int b    = blockIdx.x * NW + warp;

    const int*   tg = tags + (size_t)b * SEQ;
    const float* lg = logits + (size_t)b * (SEQ * TAGS);
    const int len = lengths[b];

    float acc = 0.0f;
    for (int s = l; s < len; s += 32) {
        int t1 = tg[s];
        acc += lg[s * TAGS + t1];
        if (s > 0) {
            int t0 = tg[s - 1];
            acc += tr[t0 * TAGS + t1];
        }
    }
#pragma unroll
    for (int k = 16; k; k >>= 1)
        acc += __shfl_xor_sync(0xffffffffu, acc, k);
    if (l == 0)
        g_partial[b] = g_logz[b] - acc;
}

// ---------------------------------------------------------------------------
// Deterministic tree reduction -> mean
// ---------------------------------------------------------------------------
__global__ void crf_reduce_kernel(float* __restrict__ out) {
    __shared__ float sm[256];
    int tid = threadIdx.x;
    float a = g_partial[tid] + g_partial[tid + 256] +
              g_partial[tid + 512] + g_partial[tid + 768];
    sm[tid] = a;
    __syncthreads();
#pragma unroll
    for (int k = 128; k; k >>= 1) {
        if (tid < k) sm[tid] += sm[tid + k];
        __syncthreads();
    }
    if (tid == 0) out[0] = sm[0] * (1.0f / 1024.0f);
}

extern "C" void kernel_launch(void* const* d_in, const int* in_sizes, int n_in,
                              void* d_out, int out_size) {
    const float* logits  = (const float*)d_in[0];
    const float* trans   = (const float*)d_in[1];
    const int*   tags    = (const int*)d_in[2];
    const int*   lengths = (const int*)d_in[3];
    float* out = (float*)d_out;

    crf_fb_kernel<<<BATCH / 2, 128>>>(logits, trans);
    crf_gold_kernel<<<BATCH / NW, NW * 32>>>(logits, trans, tags, lengths);
    crf_reduce_kernel<<<1, 256>>>(out);
}